// round 1
// baseline (speedup 1.0000x reference)
#include <cuda_runtime.h>

// Upsample_72619307041391
// x: (32, 512, 512, 1) f32, kernel: (4,4) f32
// out: (32, 1024, 1024, 1) f32
//
// out = conv1d_horiz( repeat2x2(x), kernel.flatten()[1x16], SAME(pad_left=7) )
// Collapsed: rows duplicated; even/odd output cols are 9/8-tap filters on x.

#define W_IN   512
#define H_IN   512
#define W_OUT  1024
#define HALO_L 4
#define HALO_R 4
#define ROW_SM (W_IN + HALO_L + HALO_R)   // 520

__global__ __launch_bounds__(256, 8)
void upfir_kernel(const float* __restrict__ x,
                  const float* __restrict__ ker,
                  float* __restrict__ out)
{
    __shared__ float sx[ROW_SM];
    __shared__ float se[9];   // even-col combined weights, offsets -4..+4
    __shared__ float so[8];   // odd-col combined weights,  offsets -3..+4

    const int tid = threadIdx.x;                 // 0..255
    const int row = blockIdx.x;                  // n*512 + r
    const float* xrow = x + (size_t)row * W_IN;

    // Stage one x-row with zero halo: sx[i] = x[row, i-4] (0 outside [0,512))
    #pragma unroll
    for (int i = tid; i < ROW_SM; i += 256) {
        int c = i - HALO_L;
        sx[i] = (c >= 0 && c < W_IN) ? __ldg(xrow + c) : 0.0f;
    }

    // Combine the 16 FIR taps into 9 even-phase + 8 odd-phase weights (warp 0)
    if (tid < 9) {
        float v;
        if (tid == 0)      v = __ldg(ker + 0);
        else if (tid == 8) v = __ldg(ker + 15);
        else               v = __ldg(ker + 2*tid - 1) + __ldg(ker + 2*tid);
        se[tid] = v;
    }
    if (tid >= 16 && tid < 24) {
        int i = tid - 16;
        so[i] = __ldg(ker + 2*i) + __ldg(ker + 2*i + 1);
    }
    __syncthreads();

    // Thread t produces output cols 4t..4t+3  (x-col pairs c=2t and c=2t+1)
    float xs[10];
    #pragma unroll
    for (int i = 0; i < 10; i++) xs[i] = sx[2*tid + i];   // x[2t-4+i]

    float e0 = 0.f, e1 = 0.f, o0 = 0.f, o1 = 0.f;
    #pragma unroll
    for (int d = 0; d < 9; d++) {
        float w = se[d];
        e0 = fmaf(w, xs[d],     e0);   // even col 4t   : x[2t + d - 4]
        e1 = fmaf(w, xs[d + 1], e1);   // even col 4t+2 : x[2t+1 + d - 4]
    }
    #pragma unroll
    for (int d = 0; d < 8; d++) {
        float w = so[d];
        o0 = fmaf(w, xs[d + 1], o0);   // odd col 4t+1 : x[2t + (d-3)]
        o1 = fmaf(w, xs[d + 2], o1);   // odd col 4t+3 : x[2t+1 + (d-3)]
    }

    float4 v = make_float4(e0, o0, e1, o1);

    const int n = row >> 9;            // row / 512
    const int r = row & 511;
    const size_t obase = (((size_t)n * 1024 + 2 * r) * W_OUT) + 4 * (size_t)tid;

    // duplicated rows 2r and 2r+1
    *reinterpret_cast<float4*>(out + obase)         = v;
    *reinterpret_cast<float4*>(out + obase + W_OUT) = v;
}

extern "C" void kernel_launch(void* const* d_in, const int* in_sizes, int n_in,
                              void* d_out, int out_size)
{
    const float* x   = (const float*)d_in[0];   // 32*512*512
    const float* ker = (const float*)d_in[1];   // 16 floats (4x4 row-major)
    float* out = (float*)d_out;                 // 32*1024*1024

    dim3 grid(32 * 512);
    dim3 block(256);
    upfir_kernel<<<grid, block>>>(x, ker, out);
}